// round 7
// baseline (speedup 1.0000x reference)
#include <cuda_runtime.h>
#include <cstdint>
#include <cstddef>

#define NSEQ 256
#define DDIM 32
#define KS2 132     // padded stride for 128-wide half tiles (16B-aligned rows)
#define LOG2E 1.4426950408889634f

typedef unsigned long long ull;

__device__ float gsum[128 * 256 * 2];   // per (bh, row, j-half) partial softmax sums

__device__ __forceinline__ float frcp(float x) {
    float r; asm("rcp.approx.f32 %0, %1;" : "=f"(r) : "f"(x)); return r;
}
__device__ __forceinline__ float fex2(float x) {
    float r; asm("ex2.approx.f32 %0, %1;" : "=f"(r) : "f"(x)); return r;
}
__device__ __forceinline__ ull pk(float lo, float hi) {
    ull r; asm("mov.b64 %0, {%1, %2};" : "=l"(r) : "f"(lo), "f"(hi)); return r;
}
__device__ __forceinline__ void upk(ull v, float& lo, float& hi) {
    asm("mov.b64 {%0, %1}, %2;" : "=f"(lo), "=f"(hi) : "l"(v));
}
__device__ __forceinline__ ull fma2(ull a, ull b, ull c) {
    ull r; asm("fma.rn.f32x2 %0, %1, %2, %3;" : "=l"(r) : "l"(a), "l"(b), "l"(c)); return r;
}
__device__ __forceinline__ ull mul2(ull a, ull b) {
    ull r; asm("mul.rn.f32x2 %0, %1, %2;" : "=l"(r) : "l"(a), "l"(b)); return r;
}
__device__ __forceinline__ ull add2(ull a, ull b) {
    ull r; asm("add.rn.f32x2 %0, %1, %2;" : "=l"(r) : "l"(a), "l"(b)); return r;
}

#define ONE2 0x3F8000003F800000ULL

// ---------------- kernel 1: scores + exp + partial row sums ----------------
__global__ __launch_bounds__(128, 5)
void gatv2_scores(const float* __restrict__ qg,
                  const float* __restrict__ kg,
                  const unsigned char* __restrict__ maskg,
                  const float* __restrict__ attng,
                  float* __restrict__ outg) {
    extern __shared__ float sm[];
    float* akT  = sm;                  // 32 x 132 : a'_d * k_jd  (a' = a*log2e), j-half
    float* ekT  = sm + 32 * KS2;       // 32 x 132 : exp(-k_jd)
    float* abuf = ekT + 32 * KS2;      // 32
    float* eqaq = abuf + 32;           // 4 warps x 4 rows x 32 d x float4(eq,eq,aq,aq)

    const int bh      = blockIdx.x >> 3;        // 0..127
    const int half    = (blockIdx.x >> 2) & 1;  // j-half
    const int quarter = blockIdx.x & 3;         // 64-row chunk
    const int b       = bh >> 3;
    const int h       = bh & 7;
    const int tid     = threadIdx.x;
    const int w       = tid >> 5;
    const int lane    = tid & 31;

    if (tid < 32) abuf[tid] = attng[h * DDIM + tid] * LOG2E;
    __syncthreads();

    // prep the 128-column half tile (transposed)
    const float* kbase = kg + (size_t)bh * NSEQ * DDIM + (size_t)half * 128 * DDIM;
    for (int idx = tid; idx < 128 * DDIM; idx += 128) {
        int j = idx >> 5, d = idx & 31;    // coalesced LDG over d
        float v = kbase[idx];
        akT[d * KS2 + j] = abuf[d] * v;
        ekT[d * KS2 + j] = __expf(-v);
    }
    __syncthreads();

    const float* qbase = qg + (size_t)bh * NSEQ * DDIM;
    float* eqw = eqaq + w * 512;

    for (int pass = 0; pass < 4; ++pass) {
        const int i0 = quarter * 64 + w * 16 + pass * 4;

        __syncwarp();
        {   // setup: lane == d; store (eq,eq,aq,aq) per (row,d)
            float av = abuf[lane];
            #pragma unroll
            for (int r = 0; r < 4; ++r) {
                float q  = qbase[(i0 + r) * DDIM + lane];
                float eq = __expf(-q);
                float aq = av * q;
                ((float4*)eqw)[r * 32 + lane] = make_float4(eq, eq, aq, aq);
            }
        }
        __syncwarp();

        ull ACC[4][2];
        #pragma unroll
        for (int r = 0; r < 4; ++r) { ACC[r][0] = 0ULL; ACC[r][1] = 0ULL; }

        #pragma unroll 4
        for (int d = 0; d < DDIM; ++d) {
            ull EQ[4], AQ[4];
            #pragma unroll
            for (int r = 0; r < 4; ++r) {
                ulonglong2 B = ((const ulonglong2*)eqw)[r * 32 + d];
                EQ[r] = B.x; AQ[r] = B.y;
            }
            ulonglong2 AK = *(const ulonglong2*)(akT + d * KS2 + 4 * lane);
            ulonglong2 EV = *(const ulonglong2*)(ekT + d * KS2 + 4 * lane);

            #pragma unroll
            for (int p = 0; p < 2; ++p) {
                ull EVp = p ? EV.y : EV.x;
                ull AKp = p ? AK.y : AK.x;
                ull T0 = fma2(EQ[0], EVp, ONE2);
                ull T1 = fma2(EQ[1], EVp, ONE2);
                ull T2 = fma2(EQ[2], EVp, ONE2);
                ull T3 = fma2(EQ[3], EVp, ONE2);
                ull PA = mul2(T0, T1);
                float al, ah; upk(PA, al, ah);
                ull RA = pk(frcp(al), frcp(ah));
                ull I0 = mul2(RA, T1);
                ull I1 = mul2(RA, T0);
                ull PB = mul2(T2, T3);
                float bl, bhf; upk(PB, bl, bhf);
                ull RB = pk(frcp(bl), frcp(bhf));
                ull I2 = mul2(RB, T3);
                ull I3 = mul2(RB, T2);
                ull S0 = add2(AKp, AQ[0]);
                ull S1 = add2(AKp, AQ[1]);
                ull S2 = add2(AKp, AQ[2]);
                ull S3 = add2(AKp, AQ[3]);
                ACC[0][p] = fma2(S0, I0, ACC[0][p]);
                ACC[1][p] = fma2(S1, I1, ACC[1][p]);
                ACC[2][p] = fma2(S2, I2, ACC[2][p]);
                ACC[3][p] = fma2(S3, I3, ACC[3][p]);
            }
        }

        // epilogue: exp (log2 domain), mask, partial sum, unnormalized store
        #pragma unroll
        for (int r = 0; r < 4; ++r) {
            const int i = i0 + r;
            float x[4];
            upk(ACC[r][0], x[0], x[1]); upk(ACC[r][1], x[2], x[3]);

            const unsigned mv = *(const unsigned*)(
                maskg + ((size_t)b * NSEQ + i) * NSEQ + half * 128 + 4 * lane);

            float e[4];
            #pragma unroll
            for (int u = 0; u < 4; ++u) {
                e[u] = fex2(x[u]);
                if ((mv >> (8 * u)) & 0xffu) e[u] = 0.f;   // masked -> exp(-inf)=0
            }
            float s = (e[0] + e[1]) + (e[2] + e[3]);
            #pragma unroll
            for (int o = 16; o > 0; o >>= 1)
                s += __shfl_xor_sync(0xffffffffu, s, o);
            if (lane == 0)
                gsum[((bh << 8) + i) * 2 + half] = s;

            float* orow = outg + ((size_t)bh * NSEQ + i) * NSEQ + half * 128 + 4 * lane;
            *(float4*)orow = make_float4(e[0], e[1], e[2], e[3]);
        }
    }
}

// ---------------- kernel 2: normalize by total row sum ----------------
__global__ __launch_bounds__(256)
void gatv2_norm(float* __restrict__ outg) {
    const int gid = blockIdx.x * 256 + threadIdx.x;   // float4 index
    const int row = gid >> 6;                          // 64 float4 per row
    const float2 sv = ((const float2*)gsum)[row];
    const float inv = frcp(sv.x + sv.y);
    float4 v = ((const float4*)outg)[gid];
    ((float4*)outg)[gid] = make_float4(v.x * inv, v.y * inv, v.z * inv, v.w * inv);
}

extern "C" void kernel_launch(void* const* d_in, const int* in_sizes, int n_in,
                              void* d_out, int out_size) {
    const float* q         = (const float*)d_in[0];
    const float* k         = (const float*)d_in[1];
    // d_in[2] = scale (unused)
    const unsigned char* m = (const unsigned char*)d_in[3];
    const float* attn      = (const float*)d_in[4];
    float* out             = (float*)d_out;

    const int smem = (2 * 32 * KS2 + 32) * (int)sizeof(float)
                   + 4 * 4 * 32 * (int)sizeof(float4);
    cudaFuncSetAttribute(gatv2_scores, cudaFuncAttributeMaxDynamicSharedMemorySize, smem);
    gatv2_scores<<<dim3(1024), 128, smem>>>(q, k, m, attn, out);
    gatv2_norm<<<dim3(8192), 256>>>(out);
}